// round 1
// baseline (speedup 1.0000x reference)
#include <cuda_runtime.h>

// Problem constants (fixed shapes per reference setup_inputs)
#define N_IN   65536
#define BATCH  128
#define N_OUTP 65536
#define M_SAMP 131072   // N_OUT * degree, degree = 2
#define TN     64       // outputs per block in main kernel

// Scratch (device globals: allocation inside kernel_launch is forbidden)
__device__ float g_actT[(size_t)N_IN * BATCH];   // 32 MB transposed, clipped activations
__device__ int2  g_pairs[M_SAMP];                // per-sample: {idx, bitcast(weight)}

// Replicate jnp.linspace(0,1,65536, float32): x[i] = fl(i * fl(1/65535)), x[last] = 1.0
__device__ __forceinline__ float gridx(int i) {
    return (i == N_IN - 1) ? 1.0f : (float)i * (1.0f / 65535.0f);
}

// ---------------------------------------------------------------------------
// Kernel 1: per-sample index + weight (batch-independent)
// idx = clip(searchsorted_left(x, sp) - 1, 0, N_in-1)  == largest i with x[i] < sp (clamped)
// w   = (sp - x[idx]) / ((x[idx+1]-x[idx]) + 1e-8)
// ---------------------------------------------------------------------------
__global__ void sample_kernel(const float* __restrict__ sp_in) {
    int m = blockIdx.x * blockDim.x + threadIdx.x;
    if (m >= M_SAMP) return;
    float sp = sp_in[m];
    sp = fminf(fmaxf(sp, 0.0f), 1.0f);

    int i = (int)(sp * 65535.0f);
    i = max(0, min(i, N_IN - 2));
    // Exact searchsorted fix-up (0-2 iterations): largest i with x[i] < sp
    while (i > 0 && gridx(i) >= sp) --i;
    while (i < N_IN - 2 && gridx(i + 1) < sp) ++i;

    float xi = gridx(i);
    float dx = gridx(i + 1) - xi;
    float w  = (sp - xi) / (dx + 1e-8f);
    g_pairs[m] = make_int2(i, __float_as_int(w));
}

// ---------------------------------------------------------------------------
// Kernel 2: clip + transpose act (B, N_in) -> actT (N_in, B)
// 32x32 smem tile, both sides coalesced.
// ---------------------------------------------------------------------------
__global__ void transpose_kernel(const float* __restrict__ act) {
    __shared__ float tile[32][33];
    const int n0 = blockIdx.x * 32;
    const int b0 = blockIdx.y * 32;
    const int tx = threadIdx.x;      // 0..31
    const int ty = threadIdx.y;      // 0..7
#pragma unroll
    for (int j = 0; j < 4; ++j) {
        float v = act[(size_t)(b0 + ty + j * 8) * N_IN + n0 + tx];
        tile[ty + j * 8][tx] = fminf(fmaxf(v, 0.0f), 1.0f);
    }
    __syncthreads();
#pragma unroll
    for (int j = 0; j < 4; ++j) {
        g_actT[(size_t)(n0 + ty + j * 8) * BATCH + b0 + tx] = tile[tx][ty + j * 8];
    }
}

// ---------------------------------------------------------------------------
// Kernel 3: main. Block = 256 threads handles TN=64 outputs x all 128 batches.
// Gathers are contiguous 512B rows of actT (float2 per thread, coalesced).
// Results staged in padded smem tile, then fully coalesced writes to out.
// ---------------------------------------------------------------------------
__global__ void __launch_bounds__(256) main_kernel(float* __restrict__ out) {
    __shared__ float tile[TN][129];            // [n-offset][batch], pad vs bank conflicts
    const int tid  = threadIdx.x;
    const int bp   = tid & 63;                 // batch-pair index (handles b = 2*bp, 2*bp+1)
    const int slot = tid >> 6;                 // 0..3 : which n's this thread covers
    const int n0   = blockIdx.x * TN;

    const float2* __restrict__ actT2  = (const float2*)g_actT;   // row stride = 64 float2
    const int4*   __restrict__ pairs4 = (const int4*)g_pairs;    // {i0, w0, i1, w1} per n

#pragma unroll 4
    for (int k = slot; k < TN; k += 4) {
        int4 s = pairs4[n0 + k];               // uniform across warp -> broadcast
        const int   i0 = s.x, i1 = s.z;
        const float w0 = __int_as_float(s.y);
        const float w1 = __int_as_float(s.w);

        float2 a00 = __ldg(&actT2[i0 * 64 + bp]);
        float2 a01 = __ldg(&actT2[i0 * 64 + 64 + bp]);
        float2 a10 = __ldg(&actT2[i1 * 64 + bp]);
        float2 a11 = __ldg(&actT2[i1 * 64 + 64 + bp]);

        float y0x = fmaf(a01.x - a00.x, w0, a00.x);
        float y0y = fmaf(a01.y - a00.y, w0, a00.y);
        float y1x = fmaf(a11.x - a10.x, w1, a10.x);
        float y1y = fmaf(a11.y - a10.y, w1, a10.y);

        tile[k][2 * bp]     = (1.0f - y0x) * (1.0f - y1x);
        tile[k][2 * bp + 1] = (1.0f - y0y) * (1.0f - y1y);
    }
    __syncthreads();

    // Coalesced write-out: 4 batch-rows per pass, 64 consecutive n per row.
    const int col = tid & 63;
    const int rb  = tid >> 6;
#pragma unroll 8
    for (int r = rb; r < BATCH; r += 4) {
        out[(size_t)r * N_OUTP + n0 + col] = tile[col][r];   // (col*129 + r) -> conflict-free
    }
}

// ---------------------------------------------------------------------------
extern "C" void kernel_launch(void* const* d_in, const int* in_sizes, int n_in,
                              void* d_out, int out_size) {
    const float* act = (const float*)d_in[0];   // (128, 65536) f32
    const float* sp  = (const float*)d_in[1];   // (65536, 2, 1) f32
    float* out       = (float*)d_out;           // (128, 65536) f32

    sample_kernel<<<M_SAMP / 256, 256>>>(sp);
    transpose_kernel<<<dim3(N_IN / 32, BATCH / 32), dim3(32, 8)>>>(act);
    main_kernel<<<N_OUTP / TN, 256>>>(out);
}

// round 2
// speedup vs baseline: 1.1267x; 1.1267x over previous
#include <cuda_runtime.h>

// Problem constants (fixed shapes per reference setup_inputs)
#define N_IN   65536
#define BATCH  128
#define N_OUTP 65536
#define M_SAMP 131072   // N_OUT * degree, degree = 2
#define TN     64       // outputs per block in main kernel

// Scratch (device globals: allocation inside kernel_launch is forbidden)
__device__ float g_actT[(size_t)N_IN * BATCH];   // 32 MB transposed, clipped activations
__device__ int2  g_pairs[M_SAMP];                // per-sample: {idx, bitcast(weight)}

// Replicate jnp.linspace(0,1,65536, float32): x[i] = fl(i * fl(1/65535)), x[last]=1.0
__device__ __forceinline__ float gridx(int i) {
    return (i == N_IN - 1) ? 1.0f : (float)i * (1.0f / 65535.0f);
}

// ---------------------------------------------------------------------------
// Kernel 1 (fused): sampling (batch-independent idx/weight) + clip/transpose.
// Grid = (2048, 4) x (32,8) threads. 8192 blocks -> 16 samples each.
// ---------------------------------------------------------------------------
__global__ void prep_kernel(const float* __restrict__ act,
                            const float* __restrict__ sp_in) {
    __shared__ float tile[32][33];
    const int tx = threadIdx.x;      // 0..31
    const int ty = threadIdx.y;      // 0..7

    // --- sampling: 16 samples per block, first half-warp only ---
    if (ty == 0 && tx < 16) {
        int m = (blockIdx.y * gridDim.x + blockIdx.x) * 16 + tx;
        float sp = sp_in[m];
        sp = fminf(fmaxf(sp, 0.0f), 1.0f);
        int i = (int)(sp * 65535.0f);
        i = max(0, min(i, N_IN - 2));
        // Exact searchsorted-left fix-up: largest i with x[i] < sp (clamped)
        while (i > 0 && gridx(i) >= sp) --i;
        while (i < N_IN - 2 && gridx(i + 1) < sp) ++i;
        float xi = gridx(i);
        float dx = gridx(i + 1) - xi;
        float w  = (sp - xi) / (dx + 1e-8f);
        g_pairs[m] = make_int2(i, __float_as_int(w));
    }

    // --- clip + transpose act (B, N_in) -> actT (N_in, B) ---
    const int n0 = blockIdx.x * 32;
    const int b0 = blockIdx.y * 32;
#pragma unroll
    for (int j = 0; j < 4; ++j) {
        // streaming read: don't let act evict actT from L2
        float v = __ldcs(&act[(size_t)(b0 + ty + j * 8) * N_IN + n0 + tx]);
        tile[ty + j * 8][tx] = fminf(fmaxf(v, 0.0f), 1.0f);
    }
    __syncthreads();
#pragma unroll
    for (int j = 0; j < 4; ++j) {
        g_actT[(size_t)(n0 + ty + j * 8) * BATCH + b0 + tx] = tile[tx][ty + j * 8];
    }
}

// ---------------------------------------------------------------------------
// Kernel 2: main. 256 threads handle TN=64 outputs x all 128 batches.
// Pair metadata staged in smem (no dependent idx->gather chain per iter).
// Gathers: LDG.128, one warp covers a full 512B batch-row of actT.
// Results staged in padded smem, then coalesced streaming writes to out.
// ---------------------------------------------------------------------------
__global__ void __launch_bounds__(256) main_kernel(float* __restrict__ out) {
    __shared__ float tile[TN][130];      // [n-offset][batch], pad 130: 8B-aligned f2 slots
    __shared__ int4  sp4[TN];            // {i0, w0, i1, w1} per output n
    const int tid = threadIdx.x;
    const int n0  = blockIdx.x * TN;

    if (tid < TN) sp4[tid] = ((const int4*)g_pairs)[n0 + tid];
    __syncthreads();

    const int q    = tid & 31;           // float4 batch group: batches 4q..4q+3
    const int slot = tid >> 5;           // 0..7 : which n's this thread covers
    const float4* __restrict__ actT4 = (const float4*)g_actT;  // row stride 32 float4

#pragma unroll 2
    for (int k = slot; k < TN; k += 8) {
        const int4 s = sp4[k];           // broadcast from smem
        const int   r0 = s.x * 32, r1 = s.z * 32;
        const float w0 = __int_as_float(s.y);
        const float w1 = __int_as_float(s.w);

        float4 a00 = __ldg(&actT4[r0 + q]);
        float4 a01 = __ldg(&actT4[r0 + 32 + q]);
        float4 a10 = __ldg(&actT4[r1 + q]);
        float4 a11 = __ldg(&actT4[r1 + 32 + q]);

        float4 r;
        r.x = (1.0f - fmaf(a01.x - a00.x, w0, a00.x)) * (1.0f - fmaf(a11.x - a10.x, w1, a10.x));
        r.y = (1.0f - fmaf(a01.y - a00.y, w0, a00.y)) * (1.0f - fmaf(a11.y - a10.y, w1, a10.y));
        r.z = (1.0f - fmaf(a01.z - a00.z, w0, a00.z)) * (1.0f - fmaf(a11.z - a10.z, w1, a10.z));
        r.w = (1.0f - fmaf(a01.w - a00.w, w0, a00.w)) * (1.0f - fmaf(a11.w - a10.w, w1, a10.w));

        *(float2*)&tile[k][4 * q]     = make_float2(r.x, r.y);
        *(float2*)&tile[k][4 * q + 2] = make_float2(r.z, r.w);
    }
    __syncthreads();

    // Coalesced streaming write-out: lanes span 64 consecutive n per batch row.
    const int col = tid & 63;
    const int rb  = tid >> 6;
#pragma unroll 8
    for (int r = rb; r < BATCH; r += 4) {
        __stcs(&out[(size_t)r * N_OUTP + n0 + col], tile[col][r]);  // stride 130 -> 2-way max
    }
}

// ---------------------------------------------------------------------------
extern "C" void kernel_launch(void* const* d_in, const int* in_sizes, int n_in,
                              void* d_out, int out_size) {
    const float* act = (const float*)d_in[0];   // (128, 65536) f32
    const float* sp  = (const float*)d_in[1];   // (65536, 2, 1) f32
    float* out       = (float*)d_out;           // (128, 65536) f32

    prep_kernel<<<dim3(N_IN / 32, BATCH / 32), dim3(32, 8)>>>(act, sp);
    main_kernel<<<N_OUTP / TN, 256>>>(out);
}

// round 7
// speedup vs baseline: 1.1895x; 1.0557x over previous
#include <cuda_runtime.h>

// Problem constants (fixed shapes per reference setup_inputs)
#define N_IN   65536
#define BATCH  128
#define N_OUTP 65536
#define M_SAMP 131072   // N_OUT * degree, degree = 2
#define TN     32       // outputs per block in main kernel

// Scratch (device globals: allocation inside kernel_launch is forbidden)
__device__ __align__(16) float g_actT[(size_t)N_IN * BATCH];  // 32 MB transposed, clipped
__device__ int2 g_pairs[M_SAMP];                 // per-sample: {idx*32 (f4 row), bitcast(w)}

// Replicate jnp.linspace(0,1,65536, float32): x[i] = fl(i * fl(1/65535)), x[last]=1.0
__device__ __forceinline__ float gridx(int i) {
    return (i == N_IN - 1) ? 1.0f : (float)i * (1.0f / 65535.0f);
}

// ---------------------------------------------------------------------------
// Kernel 1 (fused): sampling + clip/transpose.
// float4 both directions via XOR-swizzled float4 tile (no padding, all 16B
// accesses aligned; swizzle keeps both phases bank-conflict-free).
// Grid (512, 4), 256 threads. Block tile: n 128 x b 32. 64 samples/block.
// ---------------------------------------------------------------------------
__global__ void __launch_bounds__(256) prep_kernel(const float* __restrict__ act,
                                                   const float* __restrict__ sp_in) {
    // logical (b, c4) lives at tile4[b][c4 ^ ((b>>2) & 7)]
    __shared__ __align__(16) float4 tile4[32][32];   // 16 KB
    const int tid = threadIdx.x;
    const int n0  = blockIdx.x * 128;
    const int b0  = blockIdx.y * 32;

    // --- sampling: 64 samples per block ---
    if (tid < 64) {
        int m = (blockIdx.y * gridDim.x + blockIdx.x) * 64 + tid;
        float sp = sp_in[m];
        sp = fminf(fmaxf(sp, 0.0f), 1.0f);
        int i = (int)(sp * 65535.0f);
        i = max(0, min(i, N_IN - 2));
        // Exact searchsorted-left fix-up: largest i with x[i] < sp (clamped)
        while (i > 0 && gridx(i) >= sp) --i;
        while (i < N_IN - 2 && gridx(i + 1) < sp) ++i;
        float xi = gridx(i);
        float dx = gridx(i + 1) - xi;
        float w  = (sp - xi) / (dx + 1e-8f);
        g_pairs[m] = make_int2(i * 32, __float_as_int(w));  // pre-scaled float4 row
    }

    // --- load: thread (tx=c4 0..31, ty 0..7) reads float4 along n ---
    const int tx = tid & 31;
    const int ty = tid >> 5;
    const float4* a4 = (const float4*)act;   // row stride N_IN/4 = 16384
#pragma unroll
    for (int j = 0; j < 4; ++j) {
        int brow = ty + 8 * j;               // local b: 0..31
        float4 v = __ldcs(&a4[(size_t)(b0 + brow) * 16384 + (n0 >> 2) + tx]);
        v.x = __saturatef(v.x);
        v.y = __saturatef(v.y);
        v.z = __saturatef(v.z);
        v.w = __saturatef(v.w);
        tile4[brow][tx ^ ((brow >> 2) & 7)] = v;   // STS.128, conflict-free
    }
    __syncthreads();

    // --- store: thread (cx 0..7, n4 0..31) does a 4x4 micro-transpose ---
    const int cx = tid & 7;                   // b-quad: batches b0+4cx..4cx+3
    const int n4 = tid >> 3;                  // n-quad: n = n0+4*n4 .. +3
    float4 m0 = tile4[4 * cx + 0][n4 ^ cx];   // LDS.128, conflict-free
    float4 m1 = tile4[4 * cx + 1][n4 ^ cx];
    float4 m2 = tile4[4 * cx + 2][n4 ^ cx];
    float4 m3 = tile4[4 * cx + 3][n4 ^ cx];

    float4* t4 = (float4*)g_actT;             // row stride BATCH/4 = 32
    size_t base = (size_t)(n0 + 4 * n4) * 32 + (b0 >> 2) + cx;
    t4[base + 0 * 32] = make_float4(m0.x, m1.x, m2.x, m3.x);
    t4[base + 1 * 32] = make_float4(m0.y, m1.y, m2.y, m3.y);
    t4[base + 2 * 32] = make_float4(m0.z, m1.z, m2.z, m3.z);
    t4[base + 3 * 32] = make_float4(m0.w, m1.w, m2.w, m3.w);
}

// ---------------------------------------------------------------------------
// Kernel 2: main. 128 threads handle TN=32 outputs x all 128 batches.
// Gathers: LDG.128, one warp covers a full 512B batch-row of actT.
// Results staged in padded smem, float2-coalesced streaming writes to out.
// ---------------------------------------------------------------------------
__global__ void __launch_bounds__(128) main_kernel(float* __restrict__ out) {
    __shared__ __align__(16) float tile[TN][130];  // row stride 520B: 8B-aligned f2 slots
    __shared__ int4 sp4[TN];             // {i0*32, w0, i1*32, w1} per output n
    const int tid = threadIdx.x;
    const int n0  = blockIdx.x * TN;

    if (tid < TN) sp4[tid] = ((const int4*)g_pairs)[n0 + tid];
    __syncthreads();

    const int q    = tid & 31;           // float4 batch group: batches 4q..4q+3
    const int slot = tid >> 5;           // 0..3 : which n's this thread covers
    const float4* __restrict__ actT4 = (const float4*)g_actT;  // row stride 32 f4

#pragma unroll 2
    for (int k = slot; k < TN; k += 4) {
        const int4 s = sp4[k];           // broadcast from smem
        const int   r0 = s.x, r1 = s.z;  // pre-scaled rows
        const float w0 = __int_as_float(s.y);
        const float w1 = __int_as_float(s.w);

        float4 a00 = __ldg(&actT4[r0 + q]);
        float4 a01 = __ldg(&actT4[r0 + 32 + q]);
        float4 a10 = __ldg(&actT4[r1 + q]);
        float4 a11 = __ldg(&actT4[r1 + 32 + q]);

        float4 r;
        r.x = (1.0f - fmaf(a01.x - a00.x, w0, a00.x)) * (1.0f - fmaf(a11.x - a10.x, w1, a10.x));
        r.y = (1.0f - fmaf(a01.y - a00.y, w0, a00.y)) * (1.0f - fmaf(a11.y - a10.y, w1, a10.y));
        r.z = (1.0f - fmaf(a01.z - a00.z, w0, a00.z)) * (1.0f - fmaf(a11.z - a10.z, w1, a10.z));
        r.w = (1.0f - fmaf(a01.w - a00.w, w0, a00.w)) * (1.0f - fmaf(a11.w - a10.w, w1, a10.w));

        float* d0 = &tile[k][4 * q];
        *(float2*)d0       = make_float2(r.x, r.y);
        *(float2*)(d0 + 2) = make_float2(r.z, r.w);
    }
    __syncthreads();

    // Coalesced streaming write-out, float2 over n: lanes span 32 consecutive n.
    const int c2 = tid & 15;             // n-pair: cols 2c2, 2c2+1
    const int rb = tid >> 4;             // 0..7
    for (int r = rb; r < BATCH; r += 8) {
        float2 v;
        v.x = tile[2 * c2 + 0][r];
        v.y = tile[2 * c2 + 1][r];
        float2* dst = (float2*)&out[(size_t)r * N_OUTP + n0 + 2 * c2];
        __stcs(dst, v);
    }
}

// ---------------------------------------------------------------------------
extern "C" void kernel_launch(void* const* d_in, const int* in_sizes, int n_in,
                              void* d_out, int out_size) {
    const float* act = (const float*)d_in[0];   // (128, 65536) f32
    const float* sp  = (const float*)d_in[1];   // (65536, 2, 1) f32
    float* out       = (float*)d_out;           // (128, 65536) f32

    prep_kernel<<<dim3(N_IN / 128, BATCH / 32), 256>>>(act, sp);
    main_kernel<<<N_OUTP / TN, 128>>>(out);
}